// round 15
// baseline (speedup 1.0000x reference)
#include <cuda_runtime.h>
#include <cuda_fp16.h>
#include <math.h>
#include <stdint.h>

#define NN 585
#define BATCH 256
#define MEM 256
#define ROWS (NN * BATCH)       // 149760
#define IROWS (73 * 256)        // 18688 internal rows
#define PLANE ((size_t)ROWS * 256)

// ---------------- scratch (static device globals; no allocation) ----------------
__device__ __align__(128) __half g_P[3 * PLANE];                 // gate-planar P_iou
__device__ __align__(128) __half g_Pfx[(size_t)IROWS * 256];     // x@Wfx^T + bfx (fp16)
__device__ __align__(128) __half g_c16[(size_t)NN * BATCH * MEM];// c_all (fp16)
__device__ __align__(128) float g_S[(size_t)64 * BATCH * 768];   // hsum @ Wiouh^T (fp32)
__device__ __align__(128) __half g_G[(size_t)512 * BATCH * MEM]; // h_children @ Wfh^T (fp16)
__device__ __align__(128) float g_biou[768];

// fp16 operands
__device__ __align__(128) __half g_Ah[(size_t)ROWS * 512];
__device__ __align__(128) __half g_Wiou[768 * 512];
__device__ __align__(128) __half g_Wfx16[256 * 512];
__device__ __align__(128) __half g_Whh[768 * 256];
__device__ __align__(128) __half g_Wf16[256 * 256];
__device__ __align__(128) __half g_HS[64 * BATCH * 256];
__device__ __align__(128) __half g_h16[(size_t)NN * BATCH * MEM];

// ---------------- helpers ----------------
__device__ __forceinline__ uint32_t smem_u32(const void* p) {
    uint32_t a;
    asm("{ .reg .u64 t; cvta.to.shared.u64 t, %1; cvt.u32.u64 %0, t; }" : "=r"(a) : "l"(p));
    return a;
}
__device__ __forceinline__ void cpa16(uint32_t dst, const void* src) {
    asm volatile("cp.async.cg.shared.global [%0], [%1], 16;" :: "r"(dst), "l"(src));
}
#define CP_COMMIT() asm volatile("cp.async.commit_group;" ::: "memory")

#define LDSM4(r, addr)                                                                  \
    asm volatile("ldmatrix.sync.aligned.m8n8.x4.shared.b16 {%0,%1,%2,%3}, [%4];"        \
                 : "=r"((r)[0]), "=r"((r)[1]), "=r"((r)[2]), "=r"((r)[3]) : "r"(addr))

#define MMAH(c, a, b0, b1)                                                              \
    asm volatile("mma.sync.aligned.m16n8k16.row.col.f32.f16.f16.f32 "                   \
                 "{%0,%1,%2,%3},{%4,%5,%6,%7},{%8,%9},{%0,%1,%2,%3};"                   \
                 : "+f"((c)[0]), "+f"((c)[1]), "+f"((c)[2]), "+f"((c)[3])               \
                 : "r"((a)[0]), "r"((a)[1]), "r"((a)[2]), "r"((a)[3]), "r"(b0), "r"(b1))

__device__ __forceinline__ float sigf(float x) { return 1.f / (1.f + expf(-x)); }

// ---------------- one-shot prepare: all converts + weight/bias packing ----------------
#define R_IN   19169280                      // ROWS*512/4
#define R_WIOU (R_IN + 98304)                // 768*512/4
#define R_WFX  (R_WIOU + 32768)              // 256*512/4
#define R_WHH  (R_WFX + 49152)               // 768*256/4
#define R_WFH  (R_WHH + 16384)               // 256*256/4
#define R_BIOU (R_WFH + 192)                 // 768/4
#define PREP_BLOCKS ((R_BIOU + 255) / 256)

__device__ __forceinline__ void cvt4(const float* x, __half* y, long long i) {
    float4 v = ((const float4*)x)[i];
    ((__half2*)y)[i * 2 + 0] = __floats2half2_rn(v.x, v.y);
    ((__half2*)y)[i * 2 + 1] = __floats2half2_rn(v.z, v.w);
}

__global__ void prepare(const float* __restrict__ inputs, const float* __restrict__ Wioux,
                        const float* __restrict__ bioux, const float* __restrict__ biouh,
                        const float* __restrict__ Wfx, const float* __restrict__ Wiouh,
                        const float* __restrict__ Wfh) {
    long long i = blockIdx.x * (long long)blockDim.x + threadIdx.x;
    if (i < R_IN)        { cvt4(inputs, g_Ah, i); }
    else if (i < R_WIOU) { cvt4(Wioux, g_Wiou, i - R_IN); }
    else if (i < R_WFX)  { cvt4(Wfx, g_Wfx16, i - R_WIOU); }
    else if (i < R_WHH)  { cvt4(Wiouh, g_Whh, i - R_WFX); }
    else if (i < R_WFH)  { cvt4(Wfh, g_Wf16, i - R_WHH); }
    else if (i < R_BIOU) {
        int r = (int)(i - R_WFH) * 4;
#pragma unroll
        for (int t = 0; t < 4; t++) g_biou[r + t] = bioux[r + t] + biouh[r + t];
    }
}

// ============ mma.sync fp16 GEMM core — 1024 threads, warp tile 16x32 ============
#define TILE_B   10240          // 128 rows * 80B
#define STAGE_B  (2 * TILE_B)
#define NSTAGE   4
#define GEMM_SMEM (NSTAGE * STAGE_B)

__device__ __forceinline__ void load_stage(uint32_t dst, const __half* A0, const __half* B0,
                                           int K, int k0, int tid) {
    // 1024 chunks of 16B: tile (A|B), 128 rows x 4 col-groups each
    int tile = tid >> 9;
    int w = tid & 511;
    int row = w >> 2, c = w & 3;
    const __half* src = (tile == 0 ? A0 : B0) + (size_t)row * K + k0 + c * 8;
    cpa16(dst + tile * TILE_B + row * 80 + c * 16, src);
    CP_COMMIT();
}

__device__ __forceinline__ void gemm_core(uint32_t sb, const __half* __restrict__ A,
                                          const __half* __restrict__ B,
                                          const float* __restrict__ bias,
                                          float* __restrict__ Cf, __half* __restrict__ Ch,
                                          int N, int K, int bx, int by) {
    const int tid = threadIdx.x;
    const int warp = tid >> 5;
    const int lane = tid & 31;
    const int wm = warp >> 2;       // 0..7 -> 16 rows each
    const int wn = warp & 3;        // 0..3 -> 32 cols each
    const int bn = bx * 128;
    const int bm = by * 128;
    const int NK = K >> 5;

    const __half* A0 = A + (size_t)bm * K;
    const __half* B0 = B + (size_t)bn * K;

#pragma unroll
    for (int s = 0; s < NSTAGE - 1; s++)
        if (s < NK) load_stage(sb + s * STAGE_B, A0, B0, K, s * 32, tid);

    float acc[4][4];
#pragma unroll
    for (int ni = 0; ni < 4; ni++)
#pragma unroll
        for (int r = 0; r < 4; r++) acc[ni][r] = 0.f;

    uint32_t aoff, boff[2];
    aoff = (uint32_t)((wm * 16 + (lane & 15)) * 80 + (lane >> 4) * 16);
#pragma unroll
    for (int np = 0; np < 2; np++)
        boff[np] = (uint32_t)((wn * 32 + np * 16 + (lane & 15)) * 80 + (lane >> 4) * 16);

    for (int k = 0; k < NK; k++) {
        int kpre = k + NSTAGE - 1;
        if (kpre < NK)
            load_stage(sb + (kpre % NSTAGE) * STAGE_B, A0, B0, K, kpre * 32, tid);
        int inflight = ((kpre < NK ? kpre : NK - 1)) - k;
        if (inflight >= 3)      asm volatile("cp.async.wait_group 3;" ::: "memory");
        else if (inflight == 2) asm volatile("cp.async.wait_group 2;" ::: "memory");
        else if (inflight == 1) asm volatile("cp.async.wait_group 1;" ::: "memory");
        else                    asm volatile("cp.async.wait_group 0;" ::: "memory");
        __syncthreads();

        uint32_t st = sb + (k % NSTAGE) * STAGE_B;
#pragma unroll
        for (int ks = 0; ks < 2; ks++) {
            uint32_t ko = ks * 32;
            uint32_t ah[4], bh[2][4];
            LDSM4(ah, st + aoff + ko);
#pragma unroll
            for (int np = 0; np < 2; np++) LDSM4(bh[np], st + TILE_B + boff[np] + ko);
#pragma unroll
            for (int ni = 0; ni < 4; ni++) {
                int np = ni >> 1, sub = ni & 1;
                MMAH(acc[ni], ah, bh[np][sub], bh[np][sub + 2]);
            }
        }
        __syncthreads();
    }

#pragma unroll
    for (int ni = 0; ni < 4; ni++) {
        int col = bn + wn * 32 + ni * 8 + (lane & 3) * 2;
        float b0 = 0.f, b1 = 0.f;
        if (bias) { b0 = bias[col]; b1 = bias[col + 1]; }
        int row = bm + wm * 16 + (lane >> 2);
        float2 v0 = make_float2(acc[ni][0] + b0, acc[ni][1] + b1);
        float2 v1 = make_float2(acc[ni][2] + b0, acc[ni][3] + b1);
        if (Ch) {
            *(__half2*)(Ch + (size_t)row * N + col) = __floats2half2_rn(v0.x, v0.y);
            *(__half2*)(Ch + (size_t)(row + 8) * N + col) = __floats2half2_rn(v1.x, v1.y);
        } else {
            *(float2*)(Cf + (size_t)row * N + col) = v0;
            *(float2*)(Cf + (size_t)(row + 8) * N + col) = v1;
        }
    }
}

// union-grid kernel: G-GEMM blocks then S-GEMM blocks
__global__ __launch_bounds__(1024, 1)
void gs_gemm(const __half* __restrict__ h16c, const __half* __restrict__ Wf,
             __half* __restrict__ G, const __half* __restrict__ HS,
             const __half* __restrict__ Whh, float* __restrict__ S, int nG) {
    extern __shared__ __align__(128) char smem[];
    uint32_t sb = smem_u32(smem);
    int bid = blockIdx.x;
    if (bid < nG) {
        gemm_core(sb, h16c, Wf, nullptr, nullptr, G, 256, 256, bid & 1, bid >> 1);
    } else {
        int b2 = bid - nG;
        gemm_core(sb, HS, Whh, nullptr, S, nullptr, 768, 256, b2 % 6, b2 / 6);
    }
}

// ============ gate-grouped iou core — 1024 threads, warp tile 16x16x3gates ============
#define GSTAGE_B 25600
#define GIOU_SMEM (NSTAGE * GSTAGE_B)
#define GIOU_BLOCKS (4 * (ROWS / 128))   // 4680

__device__ __forceinline__ void giou_load_stage(uint32_t dst, const __half* A0,
                                                const __half* W, int bn, int k0, int tid) {
#pragma unroll
    for (int i = 0; i < 2; i++) {
        int chunk = tid + i * 1024;       // need 1280
        if (chunk < 1280) {
            int r = chunk >> 2, c = chunk & 3;
            const __half* src;
            if (r < 128) {
                src = A0 + (size_t)r * 512 + k0 + c * 8;
            } else {
                int rb = r - 128;
                int gg = rb >> 6, wr = rb & 63;
                src = W + (size_t)(gg * 256 + bn + wr) * 512 + k0 + c * 8;
            }
            cpa16(dst + r * 80 + c * 16, src);
        }
    }
    CP_COMMIT();
}

__device__ __forceinline__ void giou_core(uint32_t sb, const __half* __restrict__ A,
                                          const __half* __restrict__ W,
                                          const float* __restrict__ biou,
                                          __half* __restrict__ P, __half* __restrict__ c16,
                                          float* __restrict__ h_all, __half* __restrict__ h16,
                                          int bx, int by) {
    const int tid = threadIdx.x;
    const int warp = tid >> 5;
    const int lane = tid & 31;
    const int wm = warp >> 2;       // 0..7 -> 16 rows each
    const int wn = warp & 3;        // 0..3 -> 16 cols each
    const int bn = bx * 64;         // gate-local col base
    const int bm = by * 128;
    const int NK = 16;              // K=512

    const __half* A0 = A + (size_t)bm * 512;

#pragma unroll
    for (int s = 0; s < NSTAGE - 1; s++)
        giou_load_stage(sb + s * GSTAGE_B, A0, W, bn, s * 32, tid);

    float acc[3][2][4];
#pragma unroll
    for (int g = 0; g < 3; g++)
#pragma unroll
        for (int ni = 0; ni < 2; ni++)
#pragma unroll
            for (int r = 0; r < 4; r++) acc[g][ni][r] = 0.f;

    uint32_t aoff, boff[3];
    aoff = (uint32_t)((wm * 16 + (lane & 15)) * 80 + (lane >> 4) * 16);
#pragma unroll
    for (int g = 0; g < 3; g++)
        boff[g] = (uint32_t)(10240 + (g * 64 + wn * 16 + (lane & 15)) * 80 + (lane >> 4) * 16);

    for (int k = 0; k < NK; k++) {
        int kpre = k + NSTAGE - 1;
        if (kpre < NK)
            giou_load_stage(sb + (kpre % NSTAGE) * GSTAGE_B, A0, W, bn, kpre * 32, tid);
        int inflight = ((kpre < NK ? kpre : NK - 1)) - k;
        if (inflight >= 3)      asm volatile("cp.async.wait_group 3;" ::: "memory");
        else if (inflight == 2) asm volatile("cp.async.wait_group 2;" ::: "memory");
        else if (inflight == 1) asm volatile("cp.async.wait_group 1;" ::: "memory");
        else                    asm volatile("cp.async.wait_group 0;" ::: "memory");
        __syncthreads();

        uint32_t st = sb + (k % NSTAGE) * GSTAGE_B;
#pragma unroll
        for (int ks = 0; ks < 2; ks++) {
            uint32_t ko = ks * 32;
            uint32_t ah[4], bh[3][4];
            LDSM4(ah, st + aoff + ko);
#pragma unroll
            for (int g = 0; g < 3; g++) LDSM4(bh[g], st + boff[g] + ko);
#pragma unroll
            for (int g = 0; g < 3; g++) {
                MMAH(acc[g][0], ah, bh[g][0], bh[g][2]);
                MMAH(acc[g][1], ah, bh[g][1], bh[g][3]);
            }
        }
        __syncthreads();
    }

    // epilogue
    const bool leaf = (by >= 146);
#pragma unroll
    for (int ni = 0; ni < 2; ni++) {
        int col = bn + wn * 16 + ni * 8 + (lane & 3) * 2;   // gate-local col 0..255
        float bi0 = biou[col],       bi1 = biou[col + 1];
        float bo0 = biou[256 + col], bo1 = biou[256 + col + 1];
        float bu0 = biou[512 + col], bu1 = biou[512 + col + 1];
        int row0 = bm + wm * 16 + (lane >> 2);
#pragma unroll
        for (int rr = 0; rr < 2; rr++) {
            int row = row0 + rr * 8;
            int ro = rr * 2;
            float pi0 = acc[0][ni][ro] + bi0, pi1 = acc[0][ni][ro + 1] + bi1;
            float po0 = acc[1][ni][ro] + bo0, po1 = acc[1][ni][ro + 1] + bo1;
            float pu0 = acc[2][ni][ro] + bu0, pu1 = acc[2][ni][ro + 1] + bu1;
            size_t off = (size_t)row * 256 + col;
            if (leaf) {
                float i0 = sigf(pi0), i1 = sigf(pi1);
                float o0 = sigf(po0), o1 = sigf(po1);
                float u0 = tanhf(pu0), u1 = tanhf(pu1);
                float c0 = i0 * u0, c1 = i1 * u1;
                float h0 = o0 * tanhf(c0), h1 = o1 * tanhf(c1);
                *(__half2*)(c16 + off) = __floats2half2_rn(c0, c1);
                *(float2*)(h_all + off) = make_float2(h0, h1);
                *(__half2*)(h16 + off) = __floats2half2_rn(h0, h1);
            } else {
                *(__half2*)(P + off) = __floats2half2_rn(pi0, pi1);
                *(__half2*)(P + PLANE + off) = __floats2half2_rn(po0, po1);
                *(__half2*)(P + 2 * PLANE + off) = __floats2half2_rn(pu0, pu1);
            }
        }
    }
}

// union-grid projection launch: giou blocks (4680) then Pfx blocks (292)
__global__ __launch_bounds__(1024, 1)
void proj_gemm(const __half* __restrict__ Ah, const __half* __restrict__ Wiou,
               const float* __restrict__ biou, const __half* __restrict__ Wfx,
               const float* __restrict__ bfx, __half* __restrict__ P,
               __half* __restrict__ Pfx, __half* __restrict__ c16,
               float* __restrict__ h_all, __half* __restrict__ h16) {
    extern __shared__ __align__(128) char smem[];
    uint32_t sb = smem_u32(smem);
    int bid = blockIdx.x;
    if (bid < GIOU_BLOCKS) {
        giou_core(sb, Ah, Wiou, biou, P, c16, h_all, h16, bid & 3, bid >> 2);
    } else {
        int b2 = bid - GIOU_BLOCKS;
        gemm_core(sb, Ah, Wfx, bfx, nullptr, Pfx, 256, 512, b2 & 1, b2 >> 1);
    }
}

// ---------------- weighted child-h sum (reads h16, fp16 out) ----------------
__global__ void prep_level(const __half* __restrict__ h16, const float* __restrict__ prob,
                           __half* __restrict__ hs, int s) {
    int idx = blockIdx.x * blockDim.x + threadIdx.x;  // L*256*256
    int m = idx & 255;
    int b = (idx >> 8) & 255;
    int nl = idx >> 16;
    int n = s + nl;
    int c0 = n * 8 + 1;
    float sum = 0.f;
#pragma unroll
    for (int j = 0; j < 8; j++) {
        float w = prob[n * 585 + c0 + j];
        float hv = __half2float(h16[((long long)(c0 + j) * 256 + b) * 256 + m]);
        sum += w * hv;
    }
    hs[idx] = __float2half(sum);
}

// ---------------- combine: gates + cell update ----------------
__global__ void combine_level(const __half* __restrict__ P, const float* __restrict__ S,
                              const __half* __restrict__ G, const __half* __restrict__ Pfx,
                              const float* __restrict__ bfh, const float* __restrict__ prob,
                              __half* __restrict__ c16, float* __restrict__ h_all,
                              __half* __restrict__ h16, int s) {
    int idx = blockIdx.x * blockDim.x + threadIdx.x;  // L*256*256
    int m = idx & 255;
    int b = (idx >> 8) & 255;
    int nl = idx >> 16;
    int n = s + nl;
    long long prow = (long long)n * 256 + b;
    size_t poff = (size_t)prow * 256 + m;
    const float* sp = S + (long long)(idx >> 8) * 768;
    float i = sigf(__half2float(P[poff]) + sp[m]);
    float o = sigf(__half2float(P[PLANE + poff]) + sp[256 + m]);
    float u = tanhf(__half2float(P[2 * PLANE + poff]) + sp[512 + m]);
    float fx = __half2float(Pfx[poff]) + bfh[m];
    float c = i * u;
    int c0 = n * 8 + 1;
    int gbase = (n - s) * 8;
#pragma unroll
    for (int j = 0; j < 8; j++) {
        float g = __half2float(G[((long long)((gbase + j) * 256 + b)) * 256 + m]);
        float w = prob[n * 585 + c0 + j];
        float f = sigf(w * g + fx);
        float cc = __half2float(c16[((long long)(c0 + j) * 256 + b) * 256 + m]);
        c += f * (w * cc);
    }
    float h = o * tanhf(c);
    c16[poff] = __float2half(c);
    h_all[poff] = h;
    h16[poff] = __float2half(h);
}

// ---------------- launch ----------------
extern "C" void kernel_launch(void* const* d_in, const int* in_sizes, int n_in,
                              void* d_out, int out_size) {
    const float* inputs = (const float*)d_in[0];
    const float* prob = (const float*)d_in[1];
    const float* Wioux = (const float*)d_in[2];
    const float* bioux = (const float*)d_in[3];
    const float* Wiouh = (const float*)d_in[4];
    const float* biouh = (const float*)d_in[5];
    const float* Wfx = (const float*)d_in[6];
    const float* bfx = (const float*)d_in[7];
    const float* Wfh = (const float*)d_in[8];
    const float* bfh = (const float*)d_in[9];
    float* h_all = (float*)d_out;

    float *Sb, *biou;
    __half *P, *Pfx16, *c16, *Gb, *Ah, *Wiou16, *Wfx16, *Whh, *Wf16, *HS, *h16;
    cudaGetSymbolAddress((void**)&P, g_P);
    cudaGetSymbolAddress((void**)&Pfx16, g_Pfx);
    cudaGetSymbolAddress((void**)&c16, g_c16);
    cudaGetSymbolAddress((void**)&Sb, g_S);
    cudaGetSymbolAddress((void**)&Gb, g_G);
    cudaGetSymbolAddress((void**)&biou, g_biou);
    cudaGetSymbolAddress((void**)&Ah, g_Ah);
    cudaGetSymbolAddress((void**)&Wiou16, g_Wiou);
    cudaGetSymbolAddress((void**)&Wfx16, g_Wfx16);
    cudaGetSymbolAddress((void**)&Whh, g_Whh);
    cudaGetSymbolAddress((void**)&Wf16, g_Wf16);
    cudaGetSymbolAddress((void**)&HS, g_HS);
    cudaGetSymbolAddress((void**)&h16, g_h16);

    cudaFuncSetAttribute(gs_gemm, cudaFuncAttributeMaxDynamicSharedMemorySize, GEMM_SMEM);
    cudaFuncSetAttribute(proj_gemm, cudaFuncAttributeMaxDynamicSharedMemorySize, GIOU_SMEM);

    // one-shot conversions + packing
    prepare<<<PREP_BLOCKS, 256>>>(inputs, Wioux, bioux, biouh, Wfx, Wiouh, Wfh);

    // fused projection: gate-grouped iou (+leaf activation) and Pfx in one launch
    proj_gemm<<<GIOU_BLOCKS + 2 * (IROWS / 128), 1024, GIOU_SMEM>>>(
        Ah, Wiou16, biou, Wfx16, bfx, P, Pfx16, c16, h_all, h16);

    // internal levels bottom-up
    const int starts[3] = {9, 1, 0};
    const int sizes[3] = {64, 8, 1};
    for (int l = 0; l < 3; l++) {
        int s = starts[l], L = sizes[l];
        int childRows = L * 8 * 256;
        int nG = 2 * (childRows / 128);
        int nS = 6 * (L * 256 / 128);
        // hsum (from h16)
        prep_level<<<(L * 256 * 256) / 256, 256>>>(h16, prob, HS, s);
        // fused: G = h16[children] @ Wfh^T  and  S = hsum @ Wiouh^T
        gs_gemm<<<nG + nS, 1024, GEMM_SMEM>>>(h16 + (size_t)(s * 8 + 1) * 256 * 256, Wf16,
                                              Gb, HS, Whh, Sb, nG);
        combine_level<<<(L * 256 * 256) / 256, 256>>>(P, Sb, Gb, Pfx16, bfh, prob,
                                                      c16, h_all, h16, s);
    }
}

// round 16
// speedup vs baseline: 1.1102x; 1.1102x over previous
#include <cuda_runtime.h>
#include <cuda_fp16.h>
#include <math.h>
#include <stdint.h>

#define NN 585
#define BATCH 256
#define MEM 256
#define ROWS (NN * BATCH)       // 149760
#define IROWS (73 * 256)        // 18688 internal rows
#define PLANE ((size_t)ROWS * 256)

// ---------------- scratch (static device globals; no allocation) ----------------
__device__ __align__(128) __half g_P[3 * PLANE];                 // gate-planar P_iou
__device__ __align__(128) __half g_Pfx[(size_t)IROWS * 256];     // x@Wfx^T + bfx (fp16)
__device__ __align__(128) __half g_c16[(size_t)NN * BATCH * MEM];// c_all (fp16)
__device__ __align__(128) float g_S[(size_t)64 * BATCH * 768];   // hsum @ Wiouh^T (fp32)
__device__ __align__(128) __half g_G[(size_t)512 * BATCH * MEM]; // h_children @ Wfh^T (fp16)
__device__ __align__(128) float g_biou[768];

// fp16 operands
__device__ __align__(128) __half g_Ah[(size_t)ROWS * 512];
__device__ __align__(128) __half g_Wiou[768 * 512];
__device__ __align__(128) __half g_Wfx16[256 * 512];
__device__ __align__(128) __half g_Whh[768 * 256];
__device__ __align__(128) __half g_Wf16[256 * 256];
__device__ __align__(128) __half g_HS[64 * BATCH * 256];
__device__ __align__(128) __half g_h16[(size_t)NN * BATCH * MEM];

// ---------------- helpers ----------------
__device__ __forceinline__ uint32_t smem_u32(const void* p) {
    uint32_t a;
    asm("{ .reg .u64 t; cvta.to.shared.u64 t, %1; cvt.u32.u64 %0, t; }" : "=r"(a) : "l"(p));
    return a;
}
__device__ __forceinline__ void cpa16(uint32_t dst, const void* src) {
    asm volatile("cp.async.cg.shared.global [%0], [%1], 16;" :: "r"(dst), "l"(src));
}
#define CP_COMMIT() asm volatile("cp.async.commit_group;" ::: "memory")

#define LDSM4(r, addr)                                                                  \
    asm volatile("ldmatrix.sync.aligned.m8n8.x4.shared.b16 {%0,%1,%2,%3}, [%4];"        \
                 : "=r"((r)[0]), "=r"((r)[1]), "=r"((r)[2]), "=r"((r)[3]) : "r"(addr))

#define MMAH(c, a, b0, b1)                                                              \
    asm volatile("mma.sync.aligned.m16n8k16.row.col.f32.f16.f16.f32 "                   \
                 "{%0,%1,%2,%3},{%4,%5,%6,%7},{%8,%9},{%0,%1,%2,%3};"                   \
                 : "+f"((c)[0]), "+f"((c)[1]), "+f"((c)[2]), "+f"((c)[3])               \
                 : "r"((a)[0]), "r"((a)[1]), "r"((a)[2]), "r"((a)[3]), "r"(b0), "r"(b1))

__device__ __forceinline__ float sigf(float x) { return 1.f / (1.f + expf(-x)); }

// ---------------- one-shot prepare: all converts + weight/bias packing ----------------
#define R_IN   19169280                      // ROWS*512/4
#define R_WIOU (R_IN + 98304)                // 768*512/4
#define R_WFX  (R_WIOU + 32768)              // 256*512/4
#define R_WHH  (R_WFX + 49152)               // 768*256/4
#define R_WFH  (R_WHH + 16384)               // 256*256/4
#define R_BIOU (R_WFH + 192)                 // 768/4
#define PREP_BLOCKS ((R_BIOU + 255) / 256)

__device__ __forceinline__ void cvt4(const float* x, __half* y, long long i) {
    float4 v = ((const float4*)x)[i];
    ((__half2*)y)[i * 2 + 0] = __floats2half2_rn(v.x, v.y);
    ((__half2*)y)[i * 2 + 1] = __floats2half2_rn(v.z, v.w);
}

__global__ void prepare(const float* __restrict__ inputs, const float* __restrict__ Wioux,
                        const float* __restrict__ bioux, const float* __restrict__ biouh,
                        const float* __restrict__ Wfx, const float* __restrict__ Wiouh,
                        const float* __restrict__ Wfh) {
    long long i = blockIdx.x * (long long)blockDim.x + threadIdx.x;
    if (i < R_IN)        { cvt4(inputs, g_Ah, i); }
    else if (i < R_WIOU) { cvt4(Wioux, g_Wiou, i - R_IN); }
    else if (i < R_WFX)  { cvt4(Wfx, g_Wfx16, i - R_WIOU); }
    else if (i < R_WHH)  { cvt4(Wiouh, g_Whh, i - R_WFX); }
    else if (i < R_WFH)  { cvt4(Wfh, g_Wf16, i - R_WHH); }
    else if (i < R_BIOU) {
        int r = (int)(i - R_WFH) * 4;
#pragma unroll
        for (int t = 0; t < 4; t++) g_biou[r + t] = bioux[r + t] + biouh[r + t];
    }
}

// ============ mma.sync fp16 GEMM core — 256 threads, CTA tile 64x128, 2 CTAs/SM ============
#define A_TILE_B 5120           // 64 rows * 80B
#define B_TILE_B 10240          // 128 rows * 80B
#define STAGE_B  (A_TILE_B + B_TILE_B)   // 15360
#define NSTAGE   3
#define GEMM_SMEM (NSTAGE * STAGE_B)     // 46080

__device__ __forceinline__ void load_stage(uint32_t dst, const __half* A0, const __half* B0,
                                           int K, int k0, int tid) {
    // 768 chunks of 16B: A 64 rows x 4 col-groups (256), B 128 rows x 4 (512)
#pragma unroll
    for (int i = 0; i < 3; i++) {
        int chunk = tid + i * 256;
        if (chunk < 256) {
            int row = chunk >> 2, c = chunk & 3;
            cpa16(dst + row * 80 + c * 16, A0 + (size_t)row * K + k0 + c * 8);
        } else {
            int w = chunk - 256;
            int row = w >> 2, c = w & 3;
            cpa16(dst + A_TILE_B + row * 80 + c * 16, B0 + (size_t)row * K + k0 + c * 8);
        }
    }
    CP_COMMIT();
}

__device__ __forceinline__ void gemm_core(uint32_t sb, const __half* __restrict__ A,
                                          const __half* __restrict__ B,
                                          const float* __restrict__ bias,
                                          float* __restrict__ Cf, __half* __restrict__ Ch,
                                          int N, int K, int bx, int by) {
    const int tid = threadIdx.x;
    const int warp = tid >> 5;
    const int lane = tid & 31;
    const int wm = warp >> 2;       // 0..1 -> 32 rows each
    const int wn = warp & 3;        // 0..3 -> 32 cols each
    const int bn = bx * 128;
    const int bm = by * 64;
    const int NK = K >> 5;

    const __half* A0 = A + (size_t)bm * K;
    const __half* B0 = B + (size_t)bn * K;

#pragma unroll
    for (int s = 0; s < NSTAGE - 1; s++)
        if (s < NK) load_stage(sb + s * STAGE_B, A0, B0, K, s * 32, tid);

    float acc[2][4][4];
#pragma unroll
    for (int mi = 0; mi < 2; mi++)
#pragma unroll
        for (int ni = 0; ni < 4; ni++)
#pragma unroll
            for (int r = 0; r < 4; r++) acc[mi][ni][r] = 0.f;

    uint32_t aoff[2], boff[2];
#pragma unroll
    for (int mi = 0; mi < 2; mi++)
        aoff[mi] = (uint32_t)((wm * 32 + mi * 16 + (lane & 15)) * 80 + (lane >> 4) * 16);
#pragma unroll
    for (int np = 0; np < 2; np++)
        boff[np] = (uint32_t)(A_TILE_B + (wn * 32 + np * 16 + (lane & 15)) * 80 +
                              (lane >> 4) * 16);

    for (int k = 0; k < NK; k++) {
        int kpre = k + NSTAGE - 1;
        if (kpre < NK)
            load_stage(sb + (kpre % NSTAGE) * STAGE_B, A0, B0, K, kpre * 32, tid);
        int inflight = ((kpre < NK ? kpre : NK - 1)) - k;
        if (inflight >= 2)      asm volatile("cp.async.wait_group 2;" ::: "memory");
        else if (inflight == 1) asm volatile("cp.async.wait_group 1;" ::: "memory");
        else                    asm volatile("cp.async.wait_group 0;" ::: "memory");
        __syncthreads();

        uint32_t st = sb + (k % NSTAGE) * STAGE_B;
#pragma unroll
        for (int ks = 0; ks < 2; ks++) {
            uint32_t ko = ks * 32;
            uint32_t ah[2][4], bh[2][4];
#pragma unroll
            for (int mi = 0; mi < 2; mi++) LDSM4(ah[mi], st + aoff[mi] + ko);
#pragma unroll
            for (int np = 0; np < 2; np++) LDSM4(bh[np], st + boff[np] + ko);
#pragma unroll
            for (int mi = 0; mi < 2; mi++)
#pragma unroll
                for (int ni = 0; ni < 4; ni++) {
                    int np = ni >> 1, sub = ni & 1;
                    MMAH(acc[mi][ni], ah[mi], bh[np][sub], bh[np][sub + 2]);
                }
        }
        __syncthreads();
    }

#pragma unroll
    for (int ni = 0; ni < 4; ni++) {
        int col = bn + wn * 32 + ni * 8 + (lane & 3) * 2;
        float b0 = 0.f, b1 = 0.f;
        if (bias) { b0 = bias[col]; b1 = bias[col + 1]; }
#pragma unroll
        for (int mi = 0; mi < 2; mi++) {
            int row = bm + wm * 32 + mi * 16 + (lane >> 2);
            float2 v0 = make_float2(acc[mi][ni][0] + b0, acc[mi][ni][1] + b1);
            float2 v1 = make_float2(acc[mi][ni][2] + b0, acc[mi][ni][3] + b1);
            if (Ch) {
                *(__half2*)(Ch + (size_t)row * N + col) = __floats2half2_rn(v0.x, v0.y);
                *(__half2*)(Ch + (size_t)(row + 8) * N + col) = __floats2half2_rn(v1.x, v1.y);
            } else {
                *(float2*)(Cf + (size_t)row * N + col) = v0;
                *(float2*)(Cf + (size_t)(row + 8) * N + col) = v1;
            }
        }
    }
}

// union-grid kernel: G-GEMM blocks then S-GEMM blocks
__global__ __launch_bounds__(256, 2)
void gs_gemm(const __half* __restrict__ h16c, const __half* __restrict__ Wf,
             __half* __restrict__ G, const __half* __restrict__ HS,
             const __half* __restrict__ Whh, float* __restrict__ S, int nG) {
    extern __shared__ __align__(128) char smem[];
    uint32_t sb = smem_u32(smem);
    int bid = blockIdx.x;
    if (bid < nG) {
        gemm_core(sb, h16c, Wf, nullptr, nullptr, G, 256, 256, bid & 1, bid >> 1);
    } else {
        int b2 = bid - nG;
        gemm_core(sb, HS, Whh, nullptr, S, nullptr, 768, 256, b2 % 6, b2 / 6);
    }
}

// ============ gate-grouped iou core — 256 threads, tile 64rows x 64cols x 3gates ============
#define GA_TILE_B 5120                    // 64 rows * 80B
#define GSTAGE_B  (GA_TILE_B + 192 * 80)  // + B 192 rows = 20480
#define GIOU_SMEM (NSTAGE * GSTAGE_B)     // 61440
#define GIOU_BLOCKS (4 * (ROWS / 64))     // 9360

__device__ __forceinline__ void giou_load_stage(uint32_t dst, const __half* A0,
                                                const __half* W, int bn, int k0, int tid) {
    // 1024 chunks: A 256 (64 rows x 4), B 768 (192 rows x 4)
#pragma unroll
    for (int i = 0; i < 4; i++) {
        int chunk = tid + i * 256;
        if (chunk < 256) {
            int row = chunk >> 2, c = chunk & 3;
            cpa16(dst + row * 80 + c * 16, A0 + (size_t)row * 512 + k0 + c * 8);
        } else {
            int w = chunk - 256;
            int r = w >> 2, c = w & 3;
            int gg = r >> 6, wr = r & 63;
            cpa16(dst + GA_TILE_B + r * 80 + c * 16,
                  W + (size_t)(gg * 256 + bn + wr) * 512 + k0 + c * 8);
        }
    }
    CP_COMMIT();
}

__device__ __forceinline__ void giou_core(uint32_t sb, const __half* __restrict__ A,
                                          const __half* __restrict__ W,
                                          const float* __restrict__ biou,
                                          __half* __restrict__ P, __half* __restrict__ c16,
                                          float* __restrict__ h_all, __half* __restrict__ h16,
                                          int bx, int by) {
    const int tid = threadIdx.x;
    const int warp = tid >> 5;
    const int lane = tid & 31;
    const int wm = warp >> 2;       // 0..1 -> 32 rows each
    const int wn = warp & 3;        // 0..3 -> 16 cols each
    const int bn = bx * 64;         // gate-local col base
    const int bm = by * 64;
    const int NK = 16;              // K=512

    const __half* A0 = A + (size_t)bm * 512;

#pragma unroll
    for (int s = 0; s < NSTAGE - 1; s++)
        giou_load_stage(sb + s * GSTAGE_B, A0, W, bn, s * 32, tid);

    float acc[2][3][2][4];
#pragma unroll
    for (int mi = 0; mi < 2; mi++)
#pragma unroll
        for (int g = 0; g < 3; g++)
#pragma unroll
            for (int ni = 0; ni < 2; ni++)
#pragma unroll
                for (int r = 0; r < 4; r++) acc[mi][g][ni][r] = 0.f;

    uint32_t aoff[2], boff[3];
#pragma unroll
    for (int mi = 0; mi < 2; mi++)
        aoff[mi] = (uint32_t)((wm * 32 + mi * 16 + (lane & 15)) * 80 + (lane >> 4) * 16);
#pragma unroll
    for (int g = 0; g < 3; g++)
        boff[g] = (uint32_t)(GA_TILE_B + (g * 64 + wn * 16 + (lane & 15)) * 80 +
                             (lane >> 4) * 16);

    for (int k = 0; k < NK; k++) {
        int kpre = k + NSTAGE - 1;
        if (kpre < NK)
            giou_load_stage(sb + (kpre % NSTAGE) * GSTAGE_B, A0, W, bn, kpre * 32, tid);
        int inflight = ((kpre < NK ? kpre : NK - 1)) - k;
        if (inflight >= 2)      asm volatile("cp.async.wait_group 2;" ::: "memory");
        else if (inflight == 1) asm volatile("cp.async.wait_group 1;" ::: "memory");
        else                    asm volatile("cp.async.wait_group 0;" ::: "memory");
        __syncthreads();

        uint32_t st = sb + (k % NSTAGE) * GSTAGE_B;
#pragma unroll
        for (int ks = 0; ks < 2; ks++) {
            uint32_t ko = ks * 32;
            uint32_t ah[2][4], bh[3][4];
#pragma unroll
            for (int mi = 0; mi < 2; mi++) LDSM4(ah[mi], st + aoff[mi] + ko);
#pragma unroll
            for (int g = 0; g < 3; g++) LDSM4(bh[g], st + boff[g] + ko);
#pragma unroll
            for (int mi = 0; mi < 2; mi++)
#pragma unroll
                for (int g = 0; g < 3; g++) {
                    MMAH(acc[mi][g][0], ah[mi], bh[g][0], bh[g][2]);
                    MMAH(acc[mi][g][1], ah[mi], bh[g][1], bh[g][3]);
                }
        }
        __syncthreads();
    }

    // epilogue: internal rows < 18688 <=> by < 292
    const bool leaf = (by >= 292);
#pragma unroll
    for (int ni = 0; ni < 2; ni++) {
        int col = bn + wn * 16 + ni * 8 + (lane & 3) * 2;   // gate-local col 0..255
        float bi0 = biou[col],       bi1 = biou[col + 1];
        float bo0 = biou[256 + col], bo1 = biou[256 + col + 1];
        float bu0 = biou[512 + col], bu1 = biou[512 + col + 1];
#pragma unroll
        for (int mi = 0; mi < 2; mi++) {
            int row0 = bm + wm * 32 + mi * 16 + (lane >> 2);
#pragma unroll
            for (int rr = 0; rr < 2; rr++) {
                int row = row0 + rr * 8;
                int ro = rr * 2;
                float pi0 = acc[mi][0][ni][ro] + bi0, pi1 = acc[mi][0][ni][ro + 1] + bi1;
                float po0 = acc[mi][1][ni][ro] + bo0, po1 = acc[mi][1][ni][ro + 1] + bo1;
                float pu0 = acc[mi][2][ni][ro] + bu0, pu1 = acc[mi][2][ni][ro + 1] + bu1;
                size_t off = (size_t)row * 256 + col;
                if (leaf) {
                    float i0 = sigf(pi0), i1 = sigf(pi1);
                    float o0 = sigf(po0), o1 = sigf(po1);
                    float u0 = tanhf(pu0), u1 = tanhf(pu1);
                    float c0 = i0 * u0, c1 = i1 * u1;
                    float h0 = o0 * tanhf(c0), h1 = o1 * tanhf(c1);
                    *(__half2*)(c16 + off) = __floats2half2_rn(c0, c1);
                    *(float2*)(h_all + off) = make_float2(h0, h1);
                    *(__half2*)(h16 + off) = __floats2half2_rn(h0, h1);
                } else {
                    *(__half2*)(P + off) = __floats2half2_rn(pi0, pi1);
                    *(__half2*)(P + PLANE + off) = __floats2half2_rn(po0, po1);
                    *(__half2*)(P + 2 * PLANE + off) = __floats2half2_rn(pu0, pu1);
                }
            }
        }
    }
}

// union-grid projection launch: giou blocks (9360) then Pfx blocks (584)
__global__ __launch_bounds__(256, 2)
void proj_gemm(const __half* __restrict__ Ah, const __half* __restrict__ Wiou,
               const float* __restrict__ biou, const __half* __restrict__ Wfx,
               const float* __restrict__ bfx, __half* __restrict__ P,
               __half* __restrict__ Pfx, __half* __restrict__ c16,
               float* __restrict__ h_all, __half* __restrict__ h16) {
    extern __shared__ __align__(128) char smem[];
    uint32_t sb = smem_u32(smem);
    int bid = blockIdx.x;
    if (bid < GIOU_BLOCKS) {
        giou_core(sb, Ah, Wiou, biou, P, c16, h_all, h16, bid & 3, bid >> 2);
    } else {
        int b2 = bid - GIOU_BLOCKS;
        gemm_core(sb, Ah, Wfx, bfx, nullptr, Pfx, 256, 512, b2 & 1, b2 >> 1);
    }
}

// ---------------- weighted child-h sum (reads h16, fp16 out) ----------------
__global__ void prep_level(const __half* __restrict__ h16, const float* __restrict__ prob,
                           __half* __restrict__ hs, int s) {
    int idx = blockIdx.x * blockDim.x + threadIdx.x;  // L*256*256
    int m = idx & 255;
    int b = (idx >> 8) & 255;
    int nl = idx >> 16;
    int n = s + nl;
    int c0 = n * 8 + 1;
    float sum = 0.f;
#pragma unroll
    for (int j = 0; j < 8; j++) {
        float w = prob[n * 585 + c0 + j];
        float hv = __half2float(h16[((long long)(c0 + j) * 256 + b) * 256 + m]);
        sum += w * hv;
    }
    hs[idx] = __float2half(sum);
}

// ---------------- combine: gates + cell update ----------------
__global__ void combine_level(const __half* __restrict__ P, const float* __restrict__ S,
                              const __half* __restrict__ G, const __half* __restrict__ Pfx,
                              const float* __restrict__ bfh, const float* __restrict__ prob,
                              __half* __restrict__ c16, float* __restrict__ h_all,
                              __half* __restrict__ h16, int s) {
    int idx = blockIdx.x * blockDim.x + threadIdx.x;  // L*256*256
    int m = idx & 255;
    int b = (idx >> 8) & 255;
    int nl = idx >> 16;
    int n = s + nl;
    long long prow = (long long)n * 256 + b;
    size_t poff = (size_t)prow * 256 + m;
    const float* sp = S + (long long)(idx >> 8) * 768;
    float i = sigf(__half2float(P[poff]) + sp[m]);
    float o = sigf(__half2float(P[PLANE + poff]) + sp[256 + m]);
    float u = tanhf(__half2float(P[2 * PLANE + poff]) + sp[512 + m]);
    float fx = __half2float(Pfx[poff]) + bfh[m];
    float c = i * u;
    int c0 = n * 8 + 1;
    int gbase = (n - s) * 8;
#pragma unroll
    for (int j = 0; j < 8; j++) {
        float g = __half2float(G[((long long)((gbase + j) * 256 + b)) * 256 + m]);
        float w = prob[n * 585 + c0 + j];
        float f = sigf(w * g + fx);
        float cc = __half2float(c16[((long long)(c0 + j) * 256 + b) * 256 + m]);
        c += f * (w * cc);
    }
    float h = o * tanhf(c);
    c16[poff] = __float2half(c);
    h_all[poff] = h;
    h16[poff] = __float2half(h);
}

// ---------------- launch ----------------
extern "C" void kernel_launch(void* const* d_in, const int* in_sizes, int n_in,
                              void* d_out, int out_size) {
    const float* inputs = (const float*)d_in[0];
    const float* prob = (const float*)d_in[1];
    const float* Wioux = (const float*)d_in[2];
    const float* bioux = (const float*)d_in[3];
    const float* Wiouh = (const float*)d_in[4];
    const float* biouh = (const float*)d_in[5];
    const float* Wfx = (const float*)d_in[6];
    const float* bfx = (const float*)d_in[7];
    const float* Wfh = (const float*)d_in[8];
    const float* bfh = (const float*)d_in[9];
    float* h_all = (float*)d_out;

    float *Sb, *biou;
    __half *P, *Pfx16, *c16, *Gb, *Ah, *Wiou16, *Wfx16, *Whh, *Wf16, *HS, *h16;
    cudaGetSymbolAddress((void**)&P, g_P);
    cudaGetSymbolAddress((void**)&Pfx16, g_Pfx);
    cudaGetSymbolAddress((void**)&c16, g_c16);
    cudaGetSymbolAddress((void**)&Sb, g_S);
    cudaGetSymbolAddress((void**)&Gb, g_G);
    cudaGetSymbolAddress((void**)&biou, g_biou);
    cudaGetSymbolAddress((void**)&Ah, g_Ah);
    cudaGetSymbolAddress((void**)&Wiou16, g_Wiou);
    cudaGetSymbolAddress((void**)&Wfx16, g_Wfx16);
    cudaGetSymbolAddress((void**)&Whh, g_Whh);
    cudaGetSymbolAddress((void**)&Wf16, g_Wf16);
    cudaGetSymbolAddress((void**)&HS, g_HS);
    cudaGetSymbolAddress((void**)&h16, g_h16);

    cudaFuncSetAttribute(gs_gemm, cudaFuncAttributeMaxDynamicSharedMemorySize, GEMM_SMEM);
    cudaFuncSetAttribute(proj_gemm, cudaFuncAttributeMaxDynamicSharedMemorySize, GIOU_SMEM);

    // one-shot conversions + packing
    prepare<<<PREP_BLOCKS, 256>>>(inputs, Wioux, bioux, biouh, Wfx, Wiouh, Wfh);

    // fused projection: gate-grouped iou (+leaf activation) and Pfx in one launch
    proj_gemm<<<GIOU_BLOCKS + 2 * (IROWS / 64), 256, GIOU_SMEM>>>(
        Ah, Wiou16, biou, Wfx16, bfx, P, Pfx16, c16, h_all, h16);

    // internal levels bottom-up
    const int starts[3] = {9, 1, 0};
    const int sizes[3] = {64, 8, 1};
    for (int l = 0; l < 3; l++) {
        int s = starts[l], L = sizes[l];
        int childRows = L * 8 * 256;
        int nG = 2 * (childRows / 64);
        int nS = 6 * (L * 256 / 64);
        // hsum (from h16)
        prep_level<<<(L * 256 * 256) / 256, 256>>>(h16, prob, HS, s);
        // fused: G = h16[children] @ Wfh^T  and  S = hsum @ Wiouh^T
        gs_gemm<<<nG + nS, 256, GEMM_SMEM>>>(h16 + (size_t)(s * 8 + 1) * 256 * 256, Wf16,
                                             Gb, HS, Whh, Sb, nG);
        combine_level<<<(L * 256 * 256) / 256, 256>>>(P, Sb, Gb, Pfx16, bfh, prob,
                                                      c16, h_all, h16, s);
    }
}